// round 16
// baseline (speedup 1.0000x reference)
#include <cuda_runtime.h>
#include <cuda_fp16.h>
#include <math.h>
#include <stdint.h>

// Problem constants
#define Bsz 64
#define Tsz 512
#define Dsz 512
#define Hsz 1024

// ===================== portable PTX helpers (sm_80+; safe for plain sm_103) ==========
__device__ __forceinline__ uint32_t smem_u32(const void* p) {
    uint32_t a;
    asm("{ .reg .u64 t; cvta.to.shared.u64 t, %1; cvt.u32.u64 %0, t; }" : "=r"(a) : "l"(p));
    return a;
}
__device__ __forceinline__ void ldsm4(uint32_t* r, uint32_t addr) {
    asm volatile("ldmatrix.sync.aligned.m8n8.x4.shared.b16 {%0,%1,%2,%3}, [%4];"
        : "=r"(r[0]), "=r"(r[1]), "=r"(r[2]), "=r"(r[3]) : "r"(addr));
}
__device__ __forceinline__ void mma16816(float* d, const uint32_t* a,
                                         uint32_t b0, uint32_t b1) {
    asm volatile(
        "mma.sync.aligned.m16n8k16.row.col.f32.f16.f16.f32 "
        "{%0,%1,%2,%3}, {%4,%5,%6,%7}, {%8,%9}, {%0,%1,%2,%3};"
        : "+f"(d[0]), "+f"(d[1]), "+f"(d[2]), "+f"(d[3])
        : "r"(a[0]), "r"(a[1]), "r"(a[2]), "r"(a[3]), "r"(b0), "r"(b1));
}
__device__ __forceinline__ void cp16(uint32_t dst, const void* src) {
    asm volatile("cp.async.cg.shared.global [%0], [%1], 16;"
        :: "r"(dst), "l"(src) : "memory");
}
#define CP_COMMIT() asm volatile("cp.async.commit_group;" ::: "memory")
#define CP_WAIT1()  asm volatile("cp.async.wait_group 1;" ::: "memory")
#define CP_WAIT0()  asm volatile("cp.async.wait_group 0;" ::: "memory")

// ===================== global scratch (__device__ arrays — allowed) =====================
// W_hh fp16 hi/lo, ldmatrix-swizzled: 32 slices x (32 j x 1024 k) = 64KB/slice.
__device__ __align__(16) unsigned char g_Wh0[32 * 65536];
__device__ __align__(16) unsigned char g_Wh1[32 * 65536];
// Stacked h splits [rows 0-63: hi, 64-127: lo] x 1024, fp16, ping-pong on t parity.
__device__ __align__(16) __half g_hA[2][128 * Hsz];
// Phase-1 fp16 splits.
__device__ __align__(16) __half g_xhi[32768 * Dsz];
__device__ __align__(16) __half g_xlo[32768 * Dsz];
__device__ __align__(16) __half g_wihi[Hsz * Dsz];
__device__ __align__(16) __half g_wilo[Hsz * Dsz];

// ===================== Prologue: W_hh -> fp16 hi/lo, ldmatrix-swizzled layout ==========
__global__ __launch_bounds__(256) void wsplit_kernel(const float* __restrict__ Whh)
{
    int j = blockIdx.x;                 // 0..1023
    int slice = j >> 5;                 // 0..31
    int jr = j & 31;
    unsigned char* b0 = g_Wh0 + (size_t)slice * 65536;
    unsigned char* b1 = g_Wh1 + (size_t)slice * 65536;
    for (int k = threadIdx.x; k < Hsz; k += 256) {
        float v = Whh[j * Hsz + k];
        __half hi = __float2half_rn(v);
        __half lo = __float2half_rn(v - __half2float(hi));
        uint32_t off = (uint32_t)jr * 2048
                     + ((((uint32_t)(k >> 3)) * 16) ^ ((uint32_t)(jr & 7) << 4))
                     + ((k & 7) << 1);
        *(__half*)(b0 + off) = hi;
        *(__half*)(b1 + off) = lo;
    }
}

// ===================== Prologue: x and W_in fp16 hi/lo (row-major) =====================
__global__ __launch_bounds__(256) void xsplit_kernel(const float* __restrict__ x)
{
    size_t i = ((size_t)blockIdx.x * 256 + threadIdx.x) * 4;
    float4 v = *(const float4*)&x[i];
    __half h0 = __float2half_rn(v.x), h1 = __float2half_rn(v.y);
    __half h2 = __float2half_rn(v.z), h3 = __float2half_rn(v.w);
    *(__half2*)&g_xhi[i]     = __halves2half2(h0, h1);
    *(__half2*)&g_xhi[i + 2] = __halves2half2(h2, h3);
    __half l0 = __float2half_rn(v.x - __half2float(h0));
    __half l1 = __float2half_rn(v.y - __half2float(h1));
    __half l2 = __float2half_rn(v.z - __half2float(h2));
    __half l3 = __float2half_rn(v.w - __half2float(h3));
    *(__half2*)&g_xlo[i]     = __halves2half2(l0, l1);
    *(__half2*)&g_xlo[i + 2] = __halves2half2(l2, l3);
}

__global__ __launch_bounds__(256) void winsplit_kernel(const float* __restrict__ Win)
{
    size_t i = ((size_t)blockIdx.x * 256 + threadIdx.x) * 4;
    float4 v = *(const float4*)&Win[i];
    __half h0 = __float2half_rn(v.x), h1 = __float2half_rn(v.y);
    __half h2 = __float2half_rn(v.z), h3 = __float2half_rn(v.w);
    *(__half2*)&g_wihi[i]     = __halves2half2(h0, h1);
    *(__half2*)&g_wihi[i + 2] = __halves2half2(h2, h3);
    __half l0 = __float2half_rn(v.x - __half2float(h0));
    __half l1 = __float2half_rn(v.y - __half2float(h1));
    __half l2 = __float2half_rn(v.z - __half2float(h2));
    __half l3 = __float2half_rn(v.w - __half2float(h3));
    *(__half2*)&g_wilo[i]     = __halves2half2(l0, l1);
    *(__half2*)&g_wilo[i + 2] = __halves2half2(l2, l3);
}

// ===================== Phase 1: tensor-core xin GEMM (unchanged) =====
#define P1_AXHI 0
#define P1_AXLO 16384
#define P1_BWHI 32768
#define P1_BWLO 49152
#define P1_BUFSZ 65536
#define P1_SMEM  131072

__global__ __launch_bounds__(256) void gemm_in_mma(
    const float* __restrict__ bin, const float* __restrict__ bias,
    float* __restrict__ out)
{
    extern __shared__ __align__(1024) char sm[];
    const uint32_t smb = smem_u32(sm);
    const int tid  = threadIdx.x;
    const int w    = tid >> 5;
    const int lane = tid & 31;
    const int m0   = blockIdx.y * 128;
    const int n0   = blockIdx.x * 128;

    const int m_off = (w & 3) * 32;
    const int n_off = (w >> 2) * 64;
    const int g  = lane >> 2;
    const int tt = lane & 3;

    const int arow = m_off + (lane & 15);
    const uint32_t a_swz = (uint32_t)(arow & 7) << 4;
    const int a_half = lane >> 4;
    const int brow = n_off + (lane & 7) + ((lane >> 4) << 3);
    const uint32_t b_swz = (uint32_t)(brow & 7) << 4;
    const int b_half = (lane >> 3) & 1;

    float d[2][8][4];
    #pragma unroll
    for (int mi = 0; mi < 2; mi++)
        #pragma unroll
        for (int nj = 0; nj < 8; nj++)
            #pragma unroll
            for (int q = 0; q < 4; q++) d[mi][nj][q] = 0.0f;

    auto stageP = [&](int s, uint32_t boff) {
        int k0 = s * 64;
        #pragma unroll
        for (int q = 0; q < 4; q++) {
            int gq = tid + q * 256;
            int r  = gq >> 3;
            int c8 = gq & 7;
            uint32_t swz = ((uint32_t)c8 * 16) ^ ((uint32_t)(r & 7) << 4);
            uint32_t rowoff = (uint32_t)r * 128 + swz;
            size_t asrc = (size_t)(m0 + r) * Dsz + k0 + c8 * 8;
            size_t bsrc = (size_t)(n0 + r) * Dsz + k0 + c8 * 8;
            cp16(smb + boff + P1_AXHI + rowoff, g_xhi  + asrc);
            cp16(smb + boff + P1_AXLO + rowoff, g_xlo  + asrc);
            cp16(smb + boff + P1_BWHI + rowoff, g_wihi + bsrc);
            cp16(smb + boff + P1_BWLO + rowoff, g_wilo + bsrc);
        }
        CP_COMMIT();
    };

    stageP(0, 0);
    #pragma unroll 1
    for (int s = 0; s < 8; s++) {
        const uint32_t cb = (s & 1) ? P1_BUFSZ : 0;
        if (s < 7) {
            stageP(s + 1, (s & 1) ? 0 : P1_BUFSZ);
            CP_WAIT1();
        } else {
            CP_WAIT0();
        }
        __syncthreads();

        #pragma unroll
        for (int i = 0; i < 4; i++) {
            const uint32_t kcol = ((uint32_t)(2 * i + a_half) * 16) ^ a_swz;
            const uint32_t kcolb = ((uint32_t)(2 * i + b_half) * 16) ^ b_swz;
            uint32_t axh[2][4], axl[2][4];
            ldsm4(axh[0], smb + cb + P1_AXHI + (uint32_t)arow * 128 + kcol);
            ldsm4(axh[1], smb + cb + P1_AXHI + (uint32_t)(arow + 16) * 128 + kcol);
            ldsm4(axl[0], smb + cb + P1_AXLO + (uint32_t)arow * 128 + kcol);
            ldsm4(axl[1], smb + cb + P1_AXLO + (uint32_t)(arow + 16) * 128 + kcol);
            #pragma unroll
            for (int nt = 0; nt < 4; nt++) {
                uint32_t bwh[4], bwl[4];
                uint32_t boffr = (uint32_t)(brow + nt * 16) * 128;
                ldsm4(bwh, smb + cb + P1_BWHI + boffr + kcolb);
                ldsm4(bwl, smb + cb + P1_BWLO + boffr + kcolb);
                #pragma unroll
                for (int mi = 0; mi < 2; mi++) {
                    mma16816(d[mi][2 * nt],     axh[mi], bwh[0], bwh[1]);
                    mma16816(d[mi][2 * nt + 1], axh[mi], bwh[2], bwh[3]);
                    mma16816(d[mi][2 * nt],     axl[mi], bwh[0], bwh[1]);
                    mma16816(d[mi][2 * nt + 1], axl[mi], bwh[2], bwh[3]);
                    mma16816(d[mi][2 * nt],     axh[mi], bwl[0], bwl[1]);
                    mma16816(d[mi][2 * nt + 1], axh[mi], bwl[2], bwl[3]);
                }
            }
        }
        __syncthreads();
    }

    #pragma unroll
    for (int nj = 0; nj < 8; nj++) {
        int col = n0 + n_off + nj * 8 + 2 * tt;
        float b0 = bin[col]     + bias[col];
        float b1 = bin[col + 1] + bias[col + 1];
        #pragma unroll
        for (int mi = 0; mi < 2; mi++) {
            int row = m0 + m_off + mi * 16 + g;
            *(float2*)&out[(size_t)row * Hsz + col] =
                make_float2(d[mi][nj][0] + b0, d[mi][nj][1] + b1);
            *(float2*)&out[(size_t)(row + 8) * Hsz + col] =
                make_float2(d[mi][nj][2] + b0, d[mi][nj][3] + b1);
        }
    }
}

// ===================== Phase 2: dataflow mma.sync scan (epoch-synchronized) =====
// CTA (q, jsl) owns 16 batches x 32 j. Producers publish g_epoch[q][jsl] = t+1
// (release) after the named barrier over the h-writing warps; consumers poll the
// producers of both k-halves in PARALLEL (warp0: 0-15, warp1: 16-31). Skew is
// bounded to 1 step, serializing the h ping-pong buffer reuse.
#define SG 128
#define QCTAS 32

#define SMEM_WHI  0
#define SMEM_WLO  65536
#define SMEM_A    131072
#define SMEM_RED  196608
#define SMEM_TOT  198656

__device__ volatile unsigned g_epoch[128];     // [q*32 + jsl]; 0 at launch; reset at end
__device__ unsigned g_cnt4[4 * 32];            // endgame sense barriers (2 toggles/launch)
__device__ volatile unsigned g_sns4[4 * 32];

__device__ __forceinline__ void quarter_barrier(int tid, unsigned& sense, int q)
{
    __syncthreads();
    if (tid == 0) {
        __threadfence();
        unsigned s2 = sense ^ 1u;
        unsigned* cnt = &g_cnt4[q * 32];
        volatile unsigned* sns = &g_sns4[q * 32];
        unsigned old = atomicAdd(cnt, 1u);
        if (old == QCTAS - 1) {
            atomicExch(cnt, 0u);
            __threadfence();
            *sns = s2;
        } else {
            while (*sns != s2) { }
        }
        __threadfence();
    }
    sense ^= 1u;
    __syncthreads();
}

__global__ __launch_bounds__(256) void rnn_scan_mma(float* __restrict__ out)
{
    extern __shared__ __align__(1024) char sm[];
    const uint32_t smb = smem_u32(sm);
    const int tid  = threadIdx.x;
    const int w    = tid >> 5;
    const int lane = tid & 31;
    const int mi   = w >> 2;             // 0 = hi rows (h writers), 1 = lo rows
    const int ni   = w & 3;              // n-tile (8 j each)
    const int g    = lane >> 2;
    const int tt   = lane & 3;

    const int jsl  = blockIdx.x & 31;    // j-slice (producer id within quarter)
    const int j0   = jsl * 32;
    const int qid  = blockIdx.x >> 5;    // batch quarter 0..3
    const int b0   = qid * 16;

    // ---- W slice -> SMEM (resident all steps) ----
    {
        const uint4* s0 = (const uint4*)(g_Wh0 + (size_t)jsl * 65536);
        const uint4* s1 = (const uint4*)(g_Wh1 + (size_t)jsl * 65536);
        uint4* d0 = (uint4*)(sm + SMEM_WHI);
        uint4* d1 = (uint4*)(sm + SMEM_WLO);
        for (int i = tid; i < 4096; i += 256) { d0[i] = s0[i]; d1[i] = s1[i]; }
    }
    __syncthreads();

    // ldmatrix lane constants
    const int arow = mi * 16 + (lane & 15);                   // A row 0..31
    const uint32_t a_base = smb + SMEM_A + (uint32_t)arow * 2048;
    const uint32_t a_swz  = (uint32_t)(arow & 7) << 4;
    const int a_half = lane >> 4;
    const int jrow = lane & 7;
    const int bgran = lane >> 3;                              // 0..3
    const uint32_t bhi_base = smb + SMEM_WHI + (uint32_t)(ni * 8 + jrow) * 2048;
    const uint32_t blo_base = smb + SMEM_WLO + (uint32_t)(ni * 8 + jrow) * 2048;
    const uint32_t b_swz = (uint32_t)jrow << 4;

    float* red = (float*)(sm + SMEM_RED);
    unsigned sense = 0;

    // ---------- t = 0: h = tanh(xin); publish epoch 1 ----------
    {
        int lb = tid >> 4;                   // local batch 0..15
        int b  = b0 + lb;
        int jq = (tid & 15) * 2;
        int j  = j0 + jq;                    // global j (== A k index)
        size_t o = (size_t)b * (Tsz * Hsz) + j;
        float2 xv = *(const float2*)&out[o];
        float h0 = tanhf(xv.x), h1 = tanhf(xv.y);
        *(float2*)&out[o] = make_float2(h0, h1);
        __half a0 = __float2half_rn(h0), a1 = __float2half_rn(h1);
        __half2 hi2 = __halves2half2(a0, a1);
        *(__half2*)&g_hA[0][b * Hsz + j] = hi2;
        __half l0 = __float2half_rn(h0 - __half2float(a0));
        __half l1 = __float2half_rn(h1 - __half2float(a1));
        __half2 lo2 = __halves2half2(l0, l1);
        *(__half2*)&g_hA[0][(64 + b) * Hsz + j] = lo2;
        // own-slice shortcut: write straight into A smem for step 1
        uint32_t cbyte = (uint32_t)(j >> 3) << 4;
        uint32_t coff  = (uint32_t)((j & 7) * 2);
        *(__half2*)(sm + SMEM_A + (uint32_t)lb * 2048
                    + (cbyte ^ ((uint32_t)(lb & 7) << 4)) + coff) = hi2;
        int ml = 16 + lb;
        *(__half2*)(sm + SMEM_A + (uint32_t)ml * 2048
                    + (cbyte ^ ((uint32_t)(ml & 7) << 4)) + coff) = lo2;
    }
    __syncthreads();
    if (tid == 0) { __threadfence(); g_epoch[qid * 32 + jsl] = 1u; }

    // ---------- t = 1..511 ----------
    for (int t = 1; t < Tsz; t++) {
        const __half* hrd = g_hA[(t + 1) & 1];
        __half* hwr = g_hA[t & 1];

        // xin prefetch (independent of epochs)
        float2 xv0, xv1;
        size_t r0 = 0, r1 = 0;
        if (mi == 0) {
            int b = b0 + g;
            int col = j0 + ni * 8 + 2 * tt;
            r0 = ((size_t)b * Tsz + t) * Hsz + col;
            r1 = ((size_t)(b + 8) * Tsz + t) * Hsz + col;
            xv0 = *(const float2*)&out[r0];
            xv1 = *(const float2*)&out[r1];
        }

        // --- PARALLEL polls: warp0 waits producers 0..15, warp1 waits 16..31 ---
        if (w < 2) {
            int p = w * 16 + lane;
            bool act = (lane < 16) && (p != jsl);
            bool ok;
            do {
                unsigned v = act ? g_epoch[qid * 32 + p] : (unsigned)t;
                ok = __all_sync(0xffffffffu, v >= (unsigned)t);
            } while (!ok);
        }
        __syncthreads();

        // --- stage k<512 (skip own slice), then k>=512 (skip own slice) ---
        #pragma unroll
        for (int s = 0; s < 8; s++) {
            int gg = tid + (s << 8);          // 0..2047
            int m  = gg >> 6;                 // A row 0..31
            int c  = gg & 63;                 // granule (k<512)
            if ((c >> 2) != jsl) {
                int hrow = (m < 16) ? (b0 + m) : (48 + b0 + m);
                cp16(smb + SMEM_A + (uint32_t)m * 2048
                     + (((uint32_t)c * 16) ^ ((uint32_t)(m & 7) << 4)),
                     hrd + (size_t)hrow * Hsz + c * 8);
            }
        }
        CP_COMMIT();
        #pragma unroll
        for (int s = 0; s < 8; s++) {
            int gg = tid + (s << 8);
            int m  = gg >> 6;
            int c  = (gg & 63) + 64;          // granule (k>=512)
            if ((c >> 2) != jsl) {
                int hrow = (m < 16) ? (b0 + m) : (48 + b0 + m);
                cp16(smb + SMEM_A + (uint32_t)m * 2048
                     + (((uint32_t)c * 16) ^ ((uint32_t)(m & 7) << 4)),
                     hrd + (size_t)hrow * Hsz + c * 8);
            }
        }
        CP_COMMIT();

        float d[4] = {0, 0, 0, 0};

        // First half: k 0..511.
        CP_WAIT1();
        __syncthreads();
        #pragma unroll 8
        for (int ii = 0; ii < 16; ii++) {
            uint32_t kbyte = ((uint32_t)(4 * ii + bgran) * 16) ^ b_swz;
            uint32_t bh[4];
            ldsm4(bh, bhi_base + kbyte);
            uint32_t bl[4];
            if (mi == 0) ldsm4(bl, blo_base + kbyte);
            #pragma unroll
            for (int s2 = 0; s2 < 2; s2++) {
                int i = 2 * ii + s2;
                uint32_t a[4];
                ldsm4(a, a_base + (((uint32_t)(2 * i + a_half) * 16) ^ a_swz));
                mma16816(d, a, bh[2 * s2], bh[2 * s2 + 1]);
                if (mi == 0) mma16816(d, a, bl[2 * s2], bl[2 * s2 + 1]);
            }
        }
        // Second half: k 512..1023.
        CP_WAIT0();
        __syncthreads();
        #pragma unroll 8
        for (int ii = 16; ii < 32; ii++) {
            uint32_t kbyte = ((uint32_t)(4 * ii + bgran) * 16) ^ b_swz;
            uint32_t bh[4];
            ldsm4(bh, bhi_base + kbyte);
            uint32_t bl[4];
            if (mi == 0) ldsm4(bl, blo_base + kbyte);
            #pragma unroll
            for (int s2 = 0; s2 < 2; s2++) {
                int i = 2 * ii + s2;
                uint32_t a[4];
                ldsm4(a, a_base + (((uint32_t)(2 * i + a_half) * 16) ^ a_swz));
                mma16816(d, a, bh[2 * s2], bh[2 * s2 + 1]);
                if (mi == 0) mma16816(d, a, bl[2 * s2], bl[2 * s2 + 1]);
            }
        }

        // lo-row warps export partials (h_lo x W_hi)
        if (mi == 1) {
            *(float4*)&red[(ni * 32 + lane) * 4] = make_float4(d[0], d[1], d[2], d[3]);
        }
        __syncthreads();

        // hi-row warps: combine, tanh, write out + h splits (global + own-slice STS),
        // then named barrier over warps 0-3 only; warp 3 lane 0 publishes the epoch.
        // Lo warps skip ahead; ordering vs next step's staging is re-established at
        // the poll __syncthreads (A reads all done: mma precedes epilogue; red reads
        // precede the named barrier; next red write is after next wait0-sync).
        if (mi == 0) {
            float4 rr = *(const float4*)&red[(ni * 32 + lane) * 4];

            float h00 = tanhf(xv0.x + d[0] + rr.x);
            float h01 = tanhf(xv0.y + d[1] + rr.y);
            float h10 = tanhf(xv1.x + d[2] + rr.z);
            float h11 = tanhf(xv1.y + d[3] + rr.w);

            *(float2*)&out[r0] = make_float2(h00, h01);
            *(float2*)&out[r1] = make_float2(h10, h11);

            if (t < Tsz - 1) {
                int b = b0 + g;
                int colj = j0 + ni * 8 + 2 * tt;          // global j == A k index
                uint32_t cbyte = (uint32_t)(colj >> 3) << 4;
                uint32_t coff  = (uint32_t)((colj & 7) * 2);
                auto emit = [&](float v0, float v1, int bb, int mrowHi) {
                    __half p0 = __float2half_rn(v0), p1 = __float2half_rn(v1);
                    __half2 hi2 = __halves2half2(p0, p1);
                    __half q0 = __float2half_rn(v0 - __half2float(p0));
                    __half q1 = __float2half_rn(v1 - __half2float(p1));
                    __half2 lo2 = __halves2half2(q0, q1);
                    *(__half2*)&hwr[bb * Hsz + colj]        = hi2;
                    *(__half2*)&hwr[(64 + bb) * Hsz + colj] = lo2;
                    int mh = mrowHi, mlr = 16 + mrowHi;
                    *(__half2*)(sm + SMEM_A + (uint32_t)mh * 2048
                                + (cbyte ^ ((uint32_t)(mh & 7) << 4)) + coff) = hi2;
                    *(__half2*)(sm + SMEM_A + (uint32_t)mlr * 2048
                                + (cbyte ^ ((uint32_t)(mlr & 7) << 4)) + coff) = lo2;
                };
                emit(h00, h01, b,     g);
                emit(h10, h11, b + 8, g + 8);
            }

            // named barrier over the 128 h-writing threads (warps 0-3)
            asm volatile("bar.sync 1, 128;" ::: "memory");
            if (tid == 96 && t < Tsz - 1) {
                __threadfence();                               // release h_t
                g_epoch[qid * 32 + jsl] = (unsigned)(t + 1);   // publish
            }
        }
    }

    // ---------- endgame: replay-safe epoch reset (2 sense toggles) ----------
    quarter_barrier(tid, sense, qid);       // all quarter CTAs done reading epochs
    if (tid == 0) g_epoch[qid * 32 + jsl] = 0u;
    quarter_barrier(tid, sense, qid);       // even toggle count -> replay-safe
}

// ===================== launch =====================
extern "C" void kernel_launch(void* const* d_in, const int* in_sizes, int n_in,
                              void* d_out, int out_size)
{
    const float* x    = (const float*)d_in[0];   // [B,T,D]
    const float* Win  = (const float*)d_in[1];   // [H,D]
    const float* bin  = (const float*)d_in[2];   // [H]
    const float* Whh  = (const float*)d_in[3];   // [H,H]
    const float* bias = (const float*)d_in[4];   // [H]
    float* out = (float*)d_out;                  // [B,T,H]

    (void)in_sizes; (void)n_in; (void)out_size;

    cudaFuncSetAttribute(rnn_scan_mma,
                         cudaFuncAttributeMaxDynamicSharedMemorySize, SMEM_TOT);
    cudaFuncSetAttribute(gemm_in_mma,
                         cudaFuncAttributeMaxDynamicSharedMemorySize, P1_SMEM);

    // Prologues: splits (independent kernels)
    wsplit_kernel<<<Hsz, 256>>>(Whh);
    xsplit_kernel<<<16384, 256>>>(x);
    winsplit_kernel<<<512, 256>>>(Win);

    // Phase 1: xin -> out (tensor cores)
    dim3 grid1(8, 256);                          // (N-tiles, M-tiles)
    gemm_in_mma<<<grid1, 256, P1_SMEM>>>(bin, bias, out);

    // Phase 2: dataflow tensor-core recurrent scan
    rnn_scan_mma<<<SG, 256, SMEM_TOT>>>(out);
}

// round 17
// speedup vs baseline: 1.1075x; 1.1075x over previous
#include <cuda_runtime.h>
#include <cuda_fp16.h>
#include <math.h>
#include <stdint.h>

// Problem constants
#define Bsz 64
#define Tsz 512
#define Dsz 512
#define Hsz 1024

// ===================== portable PTX helpers (sm_80+; safe for plain sm_103) ==========
__device__ __forceinline__ uint32_t smem_u32(const void* p) {
    uint32_t a;
    asm("{ .reg .u64 t; cvta.to.shared.u64 t, %1; cvt.u32.u64 %0, t; }" : "=r"(a) : "l"(p));
    return a;
}
__device__ __forceinline__ void ldsm4(uint32_t* r, uint32_t addr) {
    asm volatile("ldmatrix.sync.aligned.m8n8.x4.shared.b16 {%0,%1,%2,%3}, [%4];"
        : "=r"(r[0]), "=r"(r[1]), "=r"(r[2]), "=r"(r[3]) : "r"(addr));
}
__device__ __forceinline__ void mma16816(float* d, const uint32_t* a,
                                         uint32_t b0, uint32_t b1) {
    asm volatile(
        "mma.sync.aligned.m16n8k16.row.col.f32.f16.f16.f32 "
        "{%0,%1,%2,%3}, {%4,%5,%6,%7}, {%8,%9}, {%0,%1,%2,%3};"
        : "+f"(d[0]), "+f"(d[1]), "+f"(d[2]), "+f"(d[3])
        : "r"(a[0]), "r"(a[1]), "r"(a[2]), "r"(a[3]), "r"(b0), "r"(b1));
}
__device__ __forceinline__ void cp16(uint32_t dst, const void* src) {
    asm volatile("cp.async.cg.shared.global [%0], [%1], 16;"
        :: "r"(dst), "l"(src) : "memory");
}
#define CP_COMMIT() asm volatile("cp.async.commit_group;" ::: "memory")
#define CP_WAIT1()  asm volatile("cp.async.wait_group 1;" ::: "memory")
#define CP_WAIT0()  asm volatile("cp.async.wait_group 0;" ::: "memory")

// ===================== global scratch (__device__ arrays — allowed) =====================
// W_hh fp16 hi/lo, ldmatrix-swizzled: 32 slices x (32 j x 1024 k) = 64KB/slice.
__device__ __align__(16) unsigned char g_Wh0[32 * 65536];
__device__ __align__(16) unsigned char g_Wh1[32 * 65536];
// Stacked h splits [rows 0-63: hi, 64-127: lo] x 1024, fp16, ping-pong on t parity.
__device__ __align__(16) __half g_hA[2][128 * Hsz];
// Phase-1 fp16 splits.
__device__ __align__(16) __half g_xhi[32768 * Dsz];
__device__ __align__(16) __half g_xlo[32768 * Dsz];
__device__ __align__(16) __half g_wihi[Hsz * Dsz];
__device__ __align__(16) __half g_wilo[Hsz * Dsz];

// ===================== Prologue: W_hh -> fp16 hi/lo, ldmatrix-swizzled layout ==========
__global__ __launch_bounds__(256) void wsplit_kernel(const float* __restrict__ Whh)
{
    int j = blockIdx.x;                 // 0..1023
    int slice = j >> 5;                 // 0..31
    int jr = j & 31;
    unsigned char* b0 = g_Wh0 + (size_t)slice * 65536;
    unsigned char* b1 = g_Wh1 + (size_t)slice * 65536;
    for (int k = threadIdx.x; k < Hsz; k += 256) {
        float v = Whh[j * Hsz + k];
        __half hi = __float2half_rn(v);
        __half lo = __float2half_rn(v - __half2float(hi));
        uint32_t off = (uint32_t)jr * 2048
                     + ((((uint32_t)(k >> 3)) * 16) ^ ((uint32_t)(jr & 7) << 4))
                     + ((k & 7) << 1);
        *(__half*)(b0 + off) = hi;
        *(__half*)(b1 + off) = lo;
    }
}

// ===================== Prologue: x and W_in fp16 hi/lo (row-major) =====================
__global__ __launch_bounds__(256) void xsplit_kernel(const float* __restrict__ x)
{
    size_t i = ((size_t)blockIdx.x * 256 + threadIdx.x) * 4;
    float4 v = *(const float4*)&x[i];
    __half h0 = __float2half_rn(v.x), h1 = __float2half_rn(v.y);
    __half h2 = __float2half_rn(v.z), h3 = __float2half_rn(v.w);
    *(__half2*)&g_xhi[i]     = __halves2half2(h0, h1);
    *(__half2*)&g_xhi[i + 2] = __halves2half2(h2, h3);
    __half l0 = __float2half_rn(v.x - __half2float(h0));
    __half l1 = __float2half_rn(v.y - __half2float(h1));
    __half l2 = __float2half_rn(v.z - __half2float(h2));
    __half l3 = __float2half_rn(v.w - __half2float(h3));
    *(__half2*)&g_xlo[i]     = __halves2half2(l0, l1);
    *(__half2*)&g_xlo[i + 2] = __halves2half2(l2, l3);
}

__global__ __launch_bounds__(256) void winsplit_kernel(const float* __restrict__ Win)
{
    size_t i = ((size_t)blockIdx.x * 256 + threadIdx.x) * 4;
    float4 v = *(const float4*)&Win[i];
    __half h0 = __float2half_rn(v.x), h1 = __float2half_rn(v.y);
    __half h2 = __float2half_rn(v.z), h3 = __float2half_rn(v.w);
    *(__half2*)&g_wihi[i]     = __halves2half2(h0, h1);
    *(__half2*)&g_wihi[i + 2] = __halves2half2(h2, h3);
    __half l0 = __float2half_rn(v.x - __half2float(h0));
    __half l1 = __float2half_rn(v.y - __half2float(h1));
    __half l2 = __float2half_rn(v.z - __half2float(h2));
    __half l3 = __float2half_rn(v.w - __half2float(h3));
    *(__half2*)&g_wilo[i]     = __halves2half2(l0, l1);
    *(__half2*)&g_wilo[i + 2] = __halves2half2(l2, l3);
}

// ===================== Phase 1: tensor-core xin GEMM (unchanged) =====
#define P1_AXHI 0
#define P1_AXLO 16384
#define P1_BWHI 32768
#define P1_BWLO 49152
#define P1_BUFSZ 65536
#define P1_SMEM  131072

__global__ __launch_bounds__(256) void gemm_in_mma(
    const float* __restrict__ bin, const float* __restrict__ bias,
    float* __restrict__ out)
{
    extern __shared__ __align__(1024) char sm[];
    const uint32_t smb = smem_u32(sm);
    const int tid  = threadIdx.x;
    const int w    = tid >> 5;
    const int lane = tid & 31;
    const int m0   = blockIdx.y * 128;
    const int n0   = blockIdx.x * 128;

    const int m_off = (w & 3) * 32;
    const int n_off = (w >> 2) * 64;
    const int g  = lane >> 2;
    const int tt = lane & 3;

    const int arow = m_off + (lane & 15);
    const uint32_t a_swz = (uint32_t)(arow & 7) << 4;
    const int a_half = lane >> 4;
    const int brow = n_off + (lane & 7) + ((lane >> 4) << 3);
    const uint32_t b_swz = (uint32_t)(brow & 7) << 4;
    const int b_half = (lane >> 3) & 1;

    float d[2][8][4];
    #pragma unroll
    for (int mi = 0; mi < 2; mi++)
        #pragma unroll
        for (int nj = 0; nj < 8; nj++)
            #pragma unroll
            for (int q = 0; q < 4; q++) d[mi][nj][q] = 0.0f;

    auto stageP = [&](int s, uint32_t boff) {
        int k0 = s * 64;
        #pragma unroll
        for (int q = 0; q < 4; q++) {
            int gq = tid + q * 256;
            int r  = gq >> 3;
            int c8 = gq & 7;
            uint32_t swz = ((uint32_t)c8 * 16) ^ ((uint32_t)(r & 7) << 4);
            uint32_t rowoff = (uint32_t)r * 128 + swz;
            size_t asrc = (size_t)(m0 + r) * Dsz + k0 + c8 * 8;
            size_t bsrc = (size_t)(n0 + r) * Dsz + k0 + c8 * 8;
            cp16(smb + boff + P1_AXHI + rowoff, g_xhi  + asrc);
            cp16(smb + boff + P1_AXLO + rowoff, g_xlo  + asrc);
            cp16(smb + boff + P1_BWHI + rowoff, g_wihi + bsrc);
            cp16(smb + boff + P1_BWLO + rowoff, g_wilo + bsrc);
        }
        CP_COMMIT();
    };

    stageP(0, 0);
    #pragma unroll 1
    for (int s = 0; s < 8; s++) {
        const uint32_t cb = (s & 1) ? P1_BUFSZ : 0;
        if (s < 7) {
            stageP(s + 1, (s & 1) ? 0 : P1_BUFSZ);
            CP_WAIT1();
        } else {
            CP_WAIT0();
        }
        __syncthreads();

        #pragma unroll
        for (int i = 0; i < 4; i++) {
            const uint32_t kcol = ((uint32_t)(2 * i + a_half) * 16) ^ a_swz;
            const uint32_t kcolb = ((uint32_t)(2 * i + b_half) * 16) ^ b_swz;
            uint32_t axh[2][4], axl[2][4];
            ldsm4(axh[0], smb + cb + P1_AXHI + (uint32_t)arow * 128 + kcol);
            ldsm4(axh[1], smb + cb + P1_AXHI + (uint32_t)(arow + 16) * 128 + kcol);
            ldsm4(axl[0], smb + cb + P1_AXLO + (uint32_t)arow * 128 + kcol);
            ldsm4(axl[1], smb + cb + P1_AXLO + (uint32_t)(arow + 16) * 128 + kcol);
            #pragma unroll
            for (int nt = 0; nt < 4; nt++) {
                uint32_t bwh[4], bwl[4];
                uint32_t boffr = (uint32_t)(brow + nt * 16) * 128;
                ldsm4(bwh, smb + cb + P1_BWHI + boffr + kcolb);
                ldsm4(bwl, smb + cb + P1_BWLO + boffr + kcolb);
                #pragma unroll
                for (int mi = 0; mi < 2; mi++) {
                    mma16816(d[mi][2 * nt],     axh[mi], bwh[0], bwh[1]);
                    mma16816(d[mi][2 * nt + 1], axh[mi], bwh[2], bwh[3]);
                    mma16816(d[mi][2 * nt],     axl[mi], bwh[0], bwh[1]);
                    mma16816(d[mi][2 * nt + 1], axl[mi], bwh[2], bwh[3]);
                    mma16816(d[mi][2 * nt],     axh[mi], bwl[0], bwl[1]);
                    mma16816(d[mi][2 * nt + 1], axh[mi], bwl[2], bwl[3]);
                }
            }
        }
        __syncthreads();
    }

    #pragma unroll
    for (int nj = 0; nj < 8; nj++) {
        int col = n0 + n_off + nj * 8 + 2 * tt;
        float b0 = bin[col]     + bias[col];
        float b1 = bin[col + 1] + bias[col + 1];
        #pragma unroll
        for (int mi = 0; mi < 2; mi++) {
            int row = m0 + m_off + mi * 16 + g;
            *(float2*)&out[(size_t)row * Hsz + col] =
                make_float2(d[mi][nj][0] + b0, d[mi][nj][1] + b1);
            *(float2*)&out[(size_t)(row + 8) * Hsz + col] =
                make_float2(d[mi][nj][2] + b0, d[mi][nj][3] + b1);
        }
    }
}

// ===================== Phase 2: dataflow mma.sync scan (epoch-synchronized) =====
// R15 structure (sequential poll->stage->poll->stage interleave) + early publish:
// producers publish right after the h-split global stores via a named barrier
// over the h-writing warps; out[] stores and own-slice STS happen after publish.
#define SG 128
#define QCTAS 32

#define SMEM_WHI  0
#define SMEM_WLO  65536
#define SMEM_A    131072
#define SMEM_RED  196608
#define SMEM_TOT  198656

__device__ volatile unsigned g_epoch[128];     // [q*32 + jsl]; 0 at launch; reset at end
__device__ unsigned g_cnt4[4 * 32];            // endgame sense barriers (2 toggles/launch)
__device__ volatile unsigned g_sns4[4 * 32];

__device__ __forceinline__ void quarter_barrier(int tid, unsigned& sense, int q)
{
    __syncthreads();
    if (tid == 0) {
        __threadfence();
        unsigned s2 = sense ^ 1u;
        unsigned* cnt = &g_cnt4[q * 32];
        volatile unsigned* sns = &g_sns4[q * 32];
        unsigned old = atomicAdd(cnt, 1u);
        if (old == QCTAS - 1) {
            atomicExch(cnt, 0u);
            __threadfence();
            *sns = s2;
        } else {
            while (*sns != s2) { }
        }
        __threadfence();
    }
    sense ^= 1u;
    __syncthreads();
}

__global__ __launch_bounds__(256) void rnn_scan_mma(float* __restrict__ out)
{
    extern __shared__ __align__(1024) char sm[];
    const uint32_t smb = smem_u32(sm);
    const int tid  = threadIdx.x;
    const int w    = tid >> 5;
    const int lane = tid & 31;
    const int mi   = w >> 2;             // 0 = hi rows (h writers), 1 = lo rows
    const int ni   = w & 3;              // n-tile (8 j each)
    const int g    = lane >> 2;
    const int tt   = lane & 3;

    const int jsl  = blockIdx.x & 31;    // j-slice (producer id within quarter)
    const int j0   = jsl * 32;
    const int qid  = blockIdx.x >> 5;    // batch quarter 0..3
    const int b0   = qid * 16;

    // ---- W slice -> SMEM (resident all steps) ----
    {
        const uint4* s0 = (const uint4*)(g_Wh0 + (size_t)jsl * 65536);
        const uint4* s1 = (const uint4*)(g_Wh1 + (size_t)jsl * 65536);
        uint4* d0 = (uint4*)(sm + SMEM_WHI);
        uint4* d1 = (uint4*)(sm + SMEM_WLO);
        for (int i = tid; i < 4096; i += 256) { d0[i] = s0[i]; d1[i] = s1[i]; }
    }
    __syncthreads();

    // ldmatrix lane constants
    const int arow = mi * 16 + (lane & 15);                   // A row 0..31
    const uint32_t a_base = smb + SMEM_A + (uint32_t)arow * 2048;
    const uint32_t a_swz  = (uint32_t)(arow & 7) << 4;
    const int a_half = lane >> 4;
    const int jrow = lane & 7;
    const int bgran = lane >> 3;                              // 0..3
    const uint32_t bhi_base = smb + SMEM_WHI + (uint32_t)(ni * 8 + jrow) * 2048;
    const uint32_t blo_base = smb + SMEM_WLO + (uint32_t)(ni * 8 + jrow) * 2048;
    const uint32_t b_swz = (uint32_t)jrow << 4;

    float* red = (float*)(sm + SMEM_RED);
    unsigned sense = 0;

    // ---------- t = 0: h = tanh(xin); publish epoch 1 ----------
    {
        int lb = tid >> 4;                   // local batch 0..15
        int b  = b0 + lb;
        int jq = (tid & 15) * 2;
        int j  = j0 + jq;                    // global j (== A k index)
        size_t o = (size_t)b * (Tsz * Hsz) + j;
        float2 xv = *(const float2*)&out[o];
        float h0 = tanhf(xv.x), h1 = tanhf(xv.y);
        *(float2*)&out[o] = make_float2(h0, h1);
        __half a0 = __float2half_rn(h0), a1 = __float2half_rn(h1);
        __half2 hi2 = __halves2half2(a0, a1);
        *(__half2*)&g_hA[0][b * Hsz + j] = hi2;
        __half l0 = __float2half_rn(h0 - __half2float(a0));
        __half l1 = __float2half_rn(h1 - __half2float(a1));
        __half2 lo2 = __halves2half2(l0, l1);
        *(__half2*)&g_hA[0][(64 + b) * Hsz + j] = lo2;
        // own-slice shortcut: write straight into A smem for step 1
        uint32_t cbyte = (uint32_t)(j >> 3) << 4;
        uint32_t coff  = (uint32_t)((j & 7) * 2);
        *(__half2*)(sm + SMEM_A + (uint32_t)lb * 2048
                    + (cbyte ^ ((uint32_t)(lb & 7) << 4)) + coff) = hi2;
        int ml = 16 + lb;
        *(__half2*)(sm + SMEM_A + (uint32_t)ml * 2048
                    + (cbyte ^ ((uint32_t)(ml & 7) << 4)) + coff) = lo2;
    }
    __syncthreads();
    if (tid == 0) { __threadfence(); g_epoch[qid * 32 + jsl] = 1u; }

    // ---------- t = 1..511 ----------
    for (int t = 1; t < Tsz; t++) {
        const __half* hrd = g_hA[(t + 1) & 1];
        __half* hwr = g_hA[t & 1];

        // xin prefetch (independent of epochs)
        float2 xv0, xv1;
        size_t r0 = 0, r1 = 0;
        if (mi == 0) {
            int b = b0 + g;
            int col = j0 + ni * 8 + 2 * tt;
            r0 = ((size_t)b * Tsz + t) * Hsz + col;
            r1 = ((size_t)(b + 8) * Tsz + t) * Hsz + col;
            xv0 = *(const float2*)&out[r0];
            xv1 = *(const float2*)&out[r1];
        }

        // --- wait producers 0..15, stage k<512 (skip own slice) ---
        if (w == 0) {
            int p = lane;
            bool act = (lane < 16) && (p != jsl);
            bool ok;
            do {
                unsigned v = act ? g_epoch[qid * 32 + p] : (unsigned)t;
                ok = __all_sync(0xffffffffu, v >= (unsigned)t);
            } while (!ok);
        }
        __syncthreads();
        #pragma unroll
        for (int s = 0; s < 8; s++) {
            int gg = tid + (s << 8);          // 0..2047
            int m  = gg >> 6;                 // A row 0..31
            int c  = gg & 63;                 // granule (k<512)
            if ((c >> 2) != jsl) {
                int hrow = (m < 16) ? (b0 + m) : (48 + b0 + m);
                cp16(smb + SMEM_A + (uint32_t)m * 2048
                     + (((uint32_t)c * 16) ^ ((uint32_t)(m & 7) << 4)),
                     hrd + (size_t)hrow * Hsz + c * 8);
            }
        }
        CP_COMMIT();

        // --- wait producers 16..31, stage k>=512 (skip own slice) ---
        if (w == 0) {
            int p = 16 + lane;
            bool act = (lane < 16) && (p != jsl);
            bool ok;
            do {
                unsigned v = act ? g_epoch[qid * 32 + p] : (unsigned)t;
                ok = __all_sync(0xffffffffu, v >= (unsigned)t);
            } while (!ok);
        }
        __syncthreads();
        #pragma unroll
        for (int s = 0; s < 8; s++) {
            int gg = tid + (s << 8);
            int m  = gg >> 6;
            int c  = (gg & 63) + 64;          // granule (k>=512)
            if ((c >> 2) != jsl) {
                int hrow = (m < 16) ? (b0 + m) : (48 + b0 + m);
                cp16(smb + SMEM_A + (uint32_t)m * 2048
                     + (((uint32_t)c * 16) ^ ((uint32_t)(m & 7) << 4)),
                     hrd + (size_t)hrow * Hsz + c * 8);
            }
        }
        CP_COMMIT();

        float d[4] = {0, 0, 0, 0};

        // First half: k 0..511.
        CP_WAIT1();
        __syncthreads();
        #pragma unroll 8
        for (int ii = 0; ii < 16; ii++) {
            uint32_t kbyte = ((uint32_t)(4 * ii + bgran) * 16) ^ b_swz;
            uint32_t bh[4];
            ldsm4(bh, bhi_base + kbyte);
            uint32_t bl[4];
            if (mi == 0) ldsm4(bl, blo_base + kbyte);
            #pragma unroll
            for (int s2 = 0; s2 < 2; s2++) {
                int i = 2 * ii + s2;
                uint32_t a[4];
                ldsm4(a, a_base + (((uint32_t)(2 * i + a_half) * 16) ^ a_swz));
                mma16816(d, a, bh[2 * s2], bh[2 * s2 + 1]);
                if (mi == 0) mma16816(d, a, bl[2 * s2], bl[2 * s2 + 1]);
            }
        }
        // Second half: k 512..1023.
        CP_WAIT0();
        __syncthreads();
        #pragma unroll 8
        for (int ii = 16; ii < 32; ii++) {
            uint32_t kbyte = ((uint32_t)(4 * ii + bgran) * 16) ^ b_swz;
            uint32_t bh[4];
            ldsm4(bh, bhi_base + kbyte);
            uint32_t bl[4];
            if (mi == 0) ldsm4(bl, blo_base + kbyte);
            #pragma unroll
            for (int s2 = 0; s2 < 2; s2++) {
                int i = 2 * ii + s2;
                uint32_t a[4];
                ldsm4(a, a_base + (((uint32_t)(2 * i + a_half) * 16) ^ a_swz));
                mma16816(d, a, bh[2 * s2], bh[2 * s2 + 1]);
                if (mi == 0) mma16816(d, a, bl[2 * s2], bl[2 * s2 + 1]);
            }
        }

        // lo-row warps export partials (h_lo x W_hi)
        if (mi == 1) {
            *(float4*)&red[(ni * 32 + lane) * 4] = make_float4(d[0], d[1], d[2], d[3]);
        }
        __syncthreads();

        // hi-row warps: combine + tanh, then EARLY PUBLISH:
        //   (1) h-split global stores (the only data consumers need)
        //   (2) named barrier over warps 0-3 (the h writers)
        //   (3) tid96 fence+publish epoch
        //   (4) out[] fp32 stores + own-slice STS, off the critical path
        // Lo warps skip to the next poll-sync; A/red hazards re-fenced there:
        // staging starts only after the CTA-wide post-poll sync, which hi warps
        // reach after their STS; red's next write is behind next wait0-sync.
        if (mi == 0) {
            float4 rr = *(const float4*)&red[(ni * 32 + lane) * 4];

            float h00 = tanhf(xv0.x + d[0] + rr.x);
            float h01 = tanhf(xv0.y + d[1] + rr.y);
            float h10 = tanhf(xv1.x + d[2] + rr.z);
            float h11 = tanhf(xv1.y + d[3] + rr.w);

            int b = b0 + g;
            int colj = j0 + ni * 8 + 2 * tt;          // global j == A k index
            __half2 hiA, loA, hiB, loB;
            if (t < Tsz - 1) {
                __half p0 = __float2half_rn(h00), p1 = __float2half_rn(h01);
                hiA = __halves2half2(p0, p1);
                loA = __halves2half2(__float2half_rn(h00 - __half2float(p0)),
                                     __float2half_rn(h01 - __half2float(p1)));
                __half q0 = __float2half_rn(h10), q1 = __float2half_rn(h11);
                hiB = __halves2half2(q0, q1);
                loB = __halves2half2(__float2half_rn(h10 - __half2float(q0)),
                                     __float2half_rn(h11 - __half2float(q1)));
                // (1) h-split global stores first
                *(__half2*)&hwr[b * Hsz + colj]              = hiA;
                *(__half2*)&hwr[(64 + b) * Hsz + colj]       = loA;
                *(__half2*)&hwr[(b + 8) * Hsz + colj]        = hiB;
                *(__half2*)&hwr[(72 + b) * Hsz + colj]       = loB;
            }

            // (2) named barrier over the 128 h-writing threads (warps 0-3)
            asm volatile("bar.sync 1, 128;" ::: "memory");
            // (3) publish
            if (tid == 96 && t < Tsz - 1) {
                __threadfence();                               // release h_t
                g_epoch[qid * 32 + jsl] = (unsigned)(t + 1);   // publish
            }

            // (4) off-critical-path stores
            *(float2*)&out[r0] = make_float2(h00, h01);
            *(float2*)&out[r1] = make_float2(h10, h11);
            if (t < Tsz - 1) {
                uint32_t cbyte = (uint32_t)(colj >> 3) << 4;
                uint32_t coff  = (uint32_t)((colj & 7) * 2);
                int mh0 = g,     ml0 = 16 + g;
                int mh1 = g + 8, ml1 = 24 + g;
                *(__half2*)(sm + SMEM_A + (uint32_t)mh0 * 2048
                            + (cbyte ^ ((uint32_t)(mh0 & 7) << 4)) + coff) = hiA;
                *(__half2*)(sm + SMEM_A + (uint32_t)ml0 * 2048
                            + (cbyte ^ ((uint32_t)(ml0 & 7) << 4)) + coff) = loA;
                *(__half2*)(sm + SMEM_A + (uint32_t)mh1 * 2048
                            + (cbyte ^ ((uint32_t)(mh1 & 7) << 4)) + coff) = hiB;
                *(__half2*)(sm + SMEM_A + (uint32_t)ml1 * 2048
                            + (cbyte ^ ((uint32_t)(ml1 & 7) << 4)) + coff) = loB;
            }
        }
    }

    // ---------- endgame: replay-safe epoch reset (2 sense toggles) ----------
    quarter_barrier(tid, sense, qid);       // all quarter CTAs done reading epochs
    if (tid == 0) g_epoch[qid * 32 + jsl] = 0u;
    quarter_barrier(tid, sense, qid);       // even toggle count -> replay-safe
}

// ===================== launch =====================
extern "C" void kernel_launch(void* const* d_in, const int* in_sizes, int n_in,
                              void* d_out, int out_size)
{
    const float* x    = (const float*)d_in[0];   // [B,T,D]
    const float* Win  = (const float*)d_in[1];   // [H,D]
    const float* bin  = (const float*)d_in[2];   // [H]
    const float* Whh  = (const float*)d_in[3];   // [H,H]
    const float* bias = (const float*)d_in[4];   // [H]
    float* out = (float*)d_out;                  // [B,T,H]

    (void)in_sizes; (void)n_in; (void)out_size;

    cudaFuncSetAttribute(rnn_scan_mma,
                         cudaFuncAttributeMaxDynamicSharedMemorySize, SMEM_TOT);
    cudaFuncSetAttribute(gemm_in_mma,
                         cudaFuncAttributeMaxDynamicSharedMemorySize, P1_SMEM);

    // Prologues: splits (independent kernels)
    wsplit_kernel<<<Hsz, 256>>>(Whh);
    xsplit_kernel<<<16384, 256>>>(x);
    winsplit_kernel<<<512, 256>>>(Win);

    // Phase 1: xin -> out (tensor cores)
    dim3 grid1(8, 256);                          // (N-tiles, M-tiles)
    gemm_in_mma<<<grid1, 256, P1_SMEM>>>(bin, bias, out);

    // Phase 2: dataflow tensor-core recurrent scan
    rnn_scan_mma<<<SG, 256, SMEM_TOT>>>(out);
}